// round 14
// baseline (speedup 1.0000x reference)
#include <cuda_runtime.h>
#include <math.h>
#include <stdint.h>

static constexpr int kB  = 2;
static constexpr int kNX = 512;
static constexpr int kNC = 4096;
static constexpr int kD  = 1024;
static constexpr int kH  = 16;
static constexpr int kHD = 64;
#define ATT_SCALE 0.125f   // HD^-0.5

// Scratch (allocation-free rule: __device__ globals)
__device__ float g_xn[kB * kNX * kD];
__device__ float g_q [kB * kNX * kD];
__device__ float g_a [kB * kNX * kD];
__device__ uint32_t g_mbits[(size_t)kB * kNX * kNC / 32];

// ---------------------------------------------------------------------------
// packed fp32 helpers (for the fp32 GEMMs)
// ---------------------------------------------------------------------------
using u64 = unsigned long long;

__device__ __forceinline__ u64 ffma2(u64 a, u64 b, u64 c) {
    u64 d;
    asm("fma.rn.f32x2 %0, %1, %2, %3;" : "=l"(d) : "l"(a), "l"(b), "l"(c));
    return d;
}
__device__ __forceinline__ u64 dup2(float v) {
    u64 d;
    asm("mov.b64 %0, {%1, %1};" : "=l"(d) : "f"(v));
    return d;
}
__device__ __forceinline__ float2 unpk(u64 v) {
    float2 f;
    asm("mov.b64 {%0, %1}, %2;" : "=f"(f.x), "=f"(f.y) : "l"(v));
    return f;
}

// ---------------------------------------------------------------------------
// tf32 mma helpers
// ---------------------------------------------------------------------------
__device__ __forceinline__ uint32_t cvt_tf32(float x) {
    uint32_t u;
    asm("cvt.rna.tf32.f32 %0, %1;" : "=r"(u) : "f"(x));
    return u;
}
__device__ __forceinline__ void mma_tf32(float c[4], const uint32_t a[4],
                                         uint32_t b0, uint32_t b1) {
    asm volatile(
        "mma.sync.aligned.m16n8k8.row.col.f32.tf32.tf32.f32 "
        "{%0,%1,%2,%3}, {%4,%5,%6,%7}, {%8,%9}, {%0,%1,%2,%3};"
        : "+f"(c[0]), "+f"(c[1]), "+f"(c[2]), "+f"(c[3])
        : "r"(a[0]), "r"(a[1]), "r"(a[2]), "r"(a[3]), "r"(b0), "r"(b1));
}

// ---------------------------------------------------------------------------
// LayerNorm
// ---------------------------------------------------------------------------
__global__ __launch_bounds__(256) void ln_kernel(
    const float* __restrict__ x, const float* __restrict__ w,
    const float* __restrict__ bb, float* __restrict__ out)
{
    int row = blockIdx.x;
    int tid = threadIdx.x;
    float4 v = reinterpret_cast<const float4*>(x + (size_t)row * kD)[tid];
    float s  = v.x + v.y + v.z + v.w;
    float sq = v.x*v.x + v.y*v.y + v.z*v.z + v.w*v.w;
    #pragma unroll
    for (int o = 16; o; o >>= 1) {
        s  += __shfl_xor_sync(0xffffffffu, s,  o);
        sq += __shfl_xor_sync(0xffffffffu, sq, o);
    }
    __shared__ float ss[8], ssq[8];
    int wid = tid >> 5, lid = tid & 31;
    if (lid == 0) { ss[wid] = s; ssq[wid] = sq; }
    __syncthreads();
    if (wid == 0) {
        s  = (lid < 8) ? ss[lid]  : 0.f;
        sq = (lid < 8) ? ssq[lid] : 0.f;
        #pragma unroll
        for (int o = 4; o; o >>= 1) {
            s  += __shfl_xor_sync(0xffffffffu, s,  o);
            sq += __shfl_xor_sync(0xffffffffu, sq, o);
        }
        if (lid == 0) { ss[0] = s; ssq[0] = sq; }
    }
    __syncthreads();
    float mu   = ss[0] * (1.f / kD);
    float var  = ssq[0] * (1.f / kD) - mu * mu;
    float rstd = rsqrtf(var + 1e-5f);
    float4 w4 = reinterpret_cast<const float4*>(w)[tid];
    float4 b4 = reinterpret_cast<const float4*>(bb)[tid];
    float4 o4;
    o4.x = (v.x - mu) * rstd * w4.x + b4.x;
    o4.y = (v.y - mu) * rstd * w4.y + b4.y;
    o4.z = (v.z - mu) * rstd * w4.z + b4.z;
    o4.w = (v.w - mu) * rstd * w4.w + b4.w;
    reinterpret_cast<float4*>(out + (size_t)row * kD)[tid] = o4;
}

// ---------------------------------------------------------------------------
// SGEMM (f32x2): C[M,N] = A[M,K] @ B[K,N] (unchanged, fp32-exact)
// ---------------------------------------------------------------------------
__device__ __forceinline__ int atrow(int k) { return k * 130 + 2 * (k & 1); }

__global__ __launch_bounds__(256) void sgemm_kernel(
    const float* __restrict__ A, const float* __restrict__ Bm,
    float* __restrict__ C, int M, int N, int K)
{
    __shared__ __align__(16) float At[16 * 130 + 8];
    __shared__ __align__(16) float Bs[16][68];

    int tid = threadIdx.x;
    int tx = tid & 15, ty = tid >> 4;
    int m0 = blockIdx.y * 128, n0 = blockIdx.x * 64;

    u64 acc[8][2];
    #pragma unroll
    for (int i = 0; i < 8; i++) { acc[i][0] = 0ull; acc[i][1] = 0ull; }

    for (int k0 = 0; k0 < K; k0 += 16) {
        #pragma unroll
        for (int j = 0; j < 2; j++) {
            int idx = tid + 256 * j;
            int m = idx >> 2, k4 = idx & 3;
            float4 v = *reinterpret_cast<const float4*>(
                A + (size_t)(m0 + m) * K + k0 + k4 * 4);
            int kk = k4 * 4;
            At[atrow(kk + 0) + m] = v.x;
            At[atrow(kk + 1) + m] = v.y;
            At[atrow(kk + 2) + m] = v.z;
            At[atrow(kk + 3) + m] = v.w;
        }
        {
            int kk = tid >> 4, n4 = tid & 15;
            float4 v = *reinterpret_cast<const float4*>(
                Bm + (size_t)(k0 + kk) * N + n0 + n4 * 4);
            *reinterpret_cast<float4*>(&Bs[kk][n4 * 4]) = v;
        }
        __syncthreads();
        const float* ab = At + ty * 8;
        #pragma unroll
        for (int kk = 0; kk < 16; kk++) {
            ulonglong2 b2 = *reinterpret_cast<const ulonglong2*>(&Bs[kk][tx * 4]);
            float4 a0 = *reinterpret_cast<const float4*>(ab);
            float4 a1 = *reinterpret_cast<const float4*>(ab + 4);
            ab += (kk & 1) ? 128 : 132;
            u64 d;
            d = dup2(a0.x); acc[0][0] = ffma2(d, b2.x, acc[0][0]); acc[0][1] = ffma2(d, b2.y, acc[0][1]);
            d = dup2(a0.y); acc[1][0] = ffma2(d, b2.x, acc[1][0]); acc[1][1] = ffma2(d, b2.y, acc[1][1]);
            d = dup2(a0.z); acc[2][0] = ffma2(d, b2.x, acc[2][0]); acc[2][1] = ffma2(d, b2.y, acc[2][1]);
            d = dup2(a0.w); acc[3][0] = ffma2(d, b2.x, acc[3][0]); acc[3][1] = ffma2(d, b2.y, acc[3][1]);
            d = dup2(a1.x); acc[4][0] = ffma2(d, b2.x, acc[4][0]); acc[4][1] = ffma2(d, b2.y, acc[4][1]);
            d = dup2(a1.y); acc[5][0] = ffma2(d, b2.x, acc[5][0]); acc[5][1] = ffma2(d, b2.y, acc[5][1]);
            d = dup2(a1.z); acc[6][0] = ffma2(d, b2.x, acc[6][0]); acc[6][1] = ffma2(d, b2.y, acc[6][1]);
            d = dup2(a1.w); acc[7][0] = ffma2(d, b2.x, acc[7][0]); acc[7][1] = ffma2(d, b2.y, acc[7][1]);
        }
        __syncthreads();
    }
    #pragma unroll
    for (int rr = 0; rr < 8; rr++) {
        float2 c01 = unpk(acc[rr][0]);
        float2 c23 = unpk(acc[rr][1]);
        float4 o = make_float4(c01.x, c01.y, c23.x, c23.y);
        *reinterpret_cast<float4*>(
            C + (size_t)(m0 + ty * 8 + rr) * N + n0 + tx * 4) = o;
    }
}

// ---------------------------------------------------------------------------
// kv0: out[b][h][n][d] = c[b][n][h*64+d]
// ---------------------------------------------------------------------------
__global__ __launch_bounds__(256) void kv0_kernel(
    const float* __restrict__ c, float4* __restrict__ out)
{
    int i = blockIdx.x * 256 + threadIdx.x;
    int d4 = i & 15;
    int n  = (i >> 4) & (kNC - 1);
    int h  = (i >> 16) & (kH - 1);
    int b  = i >> 20;
    const float4* src = reinterpret_cast<const float4*>(c);
    out[i] = src[(size_t)(b * kNC + n) * (kD / 4) + h * 16 + d4];
}

// ---------------------------------------------------------------------------
// mask bit-pack prepass: 32 int32 -> 1 uint32 via ballot
// ---------------------------------------------------------------------------
__global__ __launch_bounds__(256) void maskbits_kernel(
    const int* __restrict__ m, uint32_t* __restrict__ bits)
{
    int i = blockIdx.x * 256 + threadIdx.x;
    uint32_t b = __ballot_sync(0xffffffffu, m[i] != 0);
    if ((threadIdx.x & 31) == 0) bits[i >> 5] = b;
}

// ---------------------------------------------------------------------------
// Flash attention, tf32 mma.sync (m16n8k8). Block = 128 thr (4 warps),
// each warp = 16 q rows x 64 keys per tile. Grid = B*H*(NX/64) = 256.
// smem: Qs/Ps [64][68] | Ks [64][68] | Vs [64][72]  (tf32-rounded fp32 bits)
// ---------------------------------------------------------------------------
static constexpr int S_QS  = 0;              // 64*68, reused as Ps
static constexpr int S_KS  = 64 * 68;        // 4352
static constexpr int S_VS  = S_KS + 64 * 68; // 8704
static constexpr int S_TOT = S_VS + 64 * 72; // 13312 floats
static constexpr int SMEM_ATTN_BYTES = S_TOT * 4;

__global__ __launch_bounds__(128) void attn_kernel(
    const float* __restrict__ q_s, const float* __restrict__ ctx,
    const uint32_t* __restrict__ bm, float* __restrict__ a_out)
{
    extern __shared__ float sm[];
    float* Qs = sm + S_QS;   // staging for Q, then Ps
    float* Ks = sm + S_KS;
    float* Vs = sm + S_VS;
    float* Ps = Qs;

    int tid  = threadIdx.x;
    int lane = tid & 31, w = tid >> 5;
    int gr = lane >> 2, q = lane & 3;
    int qt = blockIdx.x & 7;
    int h  = (blockIdx.x >> 3) & 15;
    int b  = blockIdx.x >> 7;
    int q0 = qt * 64;

    // ---- stage Q tile (scaled + tf32-rounded) ----
    {
        const float* src = q_s + ((size_t)(b * kNX + q0)) * kD + h * kHD;
        #pragma unroll
        for (int j = 0; j < 8; j++) {
            int idx = tid + 128 * j;
            int r = idx >> 4, c4 = idx & 15;
            float4 v = *reinterpret_cast<const float4*>(src + (size_t)r * kD + c4 * 4);
            uint4 u;
            u.x = cvt_tf32(v.x * ATT_SCALE);
            u.y = cvt_tf32(v.y * ATT_SCALE);
            u.z = cvt_tf32(v.z * ATT_SCALE);
            u.w = cvt_tf32(v.w * ATT_SCALE);
            *reinterpret_cast<uint4*>(&Qs[r * 68 + c4 * 4]) = u;
        }
    }
    __syncthreads();

    // ---- extract Q A-fragments (held in regs for whole kernel) ----
    uint32_t qa[8][4];
    int qr0 = (w * 16 + gr) * 68;
    int qr1 = qr0 + 8 * 68;
    #pragma unroll
    for (int s = 0; s < 8; s++) {
        qa[s][0] = __float_as_uint(Qs[qr0 + s * 8 + q]);
        qa[s][1] = __float_as_uint(Qs[qr1 + s * 8 + q]);
        qa[s][2] = __float_as_uint(Qs[qr0 + s * 8 + q + 4]);
        qa[s][3] = __float_as_uint(Qs[qr1 + s * 8 + q + 4]);
    }
    __syncthreads();   // Qs now free -> Ps

    float o[8][4];
    #pragma unroll
    for (int dt = 0; dt < 8; dt++)
        #pragma unroll
        for (int c = 0; c < 4; c++) o[dt][c] = 0.f;
    float mi0 = -1e30f, mi1 = -1e30f, li0 = 0.f, li1 = 0.f;

    const uint32_t* mrow0 = bm + ((size_t)(b * kNX + q0 + w * 16 + gr)) * (kNC / 32);
    const uint32_t* mrow1 = mrow0 + 8 * (kNC / 32);

    const int NT = kNX / 64 + kNC / 64;   // 72
    for (int t = 0; t < NT; t++) {
        __syncthreads();   // prev-tile PV reads done before refill
        const float* src = (t < 8)
            ? q_s + ((size_t)(b * kNX + t * 64)) * kD + h * kHD
            : ctx + ((size_t)(b * kNC + (t - 8) * 64)) * kD + h * kHD;
        #pragma unroll
        for (int j = 0; j < 8; j++) {
            int idx = tid + 128 * j;
            int r = idx >> 4, c4 = idx & 15;
            float4 v = *reinterpret_cast<const float4*>(src + (size_t)r * kD + c4 * 4);
            uint4 u;
            u.x = cvt_tf32(v.x); u.y = cvt_tf32(v.y);
            u.z = cvt_tf32(v.z); u.w = cvt_tf32(v.w);
            *reinterpret_cast<uint4*>(&Ks[r * 68 + c4 * 4]) = u;
            *reinterpret_cast<uint4*>(&Vs[r * 72 + c4 * 4]) = u;
        }
        bool masked = (t >= 8);
        uint2 mw0, mw1;
        if (masked) {
            mw0 = *reinterpret_cast<const uint2*>(mrow0 + (t - 8) * 2);
            mw1 = *reinterpret_cast<const uint2*>(mrow1 + (t - 8) * 2);
        }
        __syncthreads();

        // ---- S = Q . K^T : 8 n-tiles x 8 k-steps of m16n8k8 ----
        float s[8][4];
        const float* kb = Ks + gr * 68 + q;
        #pragma unroll
        for (int j = 0; j < 8; j++) {
            s[j][0] = 0.f; s[j][1] = 0.f; s[j][2] = 0.f; s[j][3] = 0.f;
            const float* kj = kb + j * (8 * 68);
            #pragma unroll
            for (int ks = 0; ks < 8; ks++) {
                uint32_t b0 = __float_as_uint(kj[ks * 8]);
                uint32_t b1 = __float_as_uint(kj[ks * 8 + 4]);
                mma_tf32(s[j], qa[ks], b0, b1);
            }
        }

        // ---- mask ----
        if (masked) {
            #pragma unroll
            for (int j = 0; j < 8; j++) {
                uint32_t w0 = (j < 4) ? mw0.x : mw0.y;
                uint32_t w1 = (j < 4) ? mw1.x : mw1.y;
                int bit = (8 * j + 2 * q) & 31;
                if (!((w0 >> bit) & 1u))       s[j][0] = -1e30f;
                if (!((w0 >> (bit + 1)) & 1u)) s[j][1] = -1e30f;
                if (!((w1 >> bit) & 1u))       s[j][2] = -1e30f;
                if (!((w1 >> (bit + 1)) & 1u)) s[j][3] = -1e30f;
            }
        }

        // ---- online softmax (rows g and g+8; 4 lanes per row) ----
        float mx0 = -1e30f, mx1 = -1e30f;
        #pragma unroll
        for (int j = 0; j < 8; j++) {
            mx0 = fmaxf(mx0, fmaxf(s[j][0], s[j][1]));
            mx1 = fmaxf(mx1, fmaxf(s[j][2], s[j][3]));
        }
        mx0 = fmaxf(mx0, __shfl_xor_sync(0xffffffffu, mx0, 1));
        mx0 = fmaxf(mx0, __shfl_xor_sync(0xffffffffu, mx0, 2));
        mx1 = fmaxf(mx1, __shfl_xor_sync(0xffffffffu, mx1, 1));
        mx1 = fmaxf(mx1, __shfl_xor_sync(0xffffffffu, mx1, 2));
        float mn0 = fmaxf(mi0, mx0), mn1 = fmaxf(mi1, mx1);
        float corr0 = __expf(mi0 - mn0), corr1 = __expf(mi1 - mn1);
        mi0 = mn0; mi1 = mn1;

        float sum0 = 0.f, sum1 = 0.f;
        int pr0 = qr0, pr1 = qr1;
        #pragma unroll
        for (int j = 0; j < 8; j++) {
            float p0 = __expf(s[j][0] - mn0);
            float p1 = __expf(s[j][1] - mn0);
            float p2 = __expf(s[j][2] - mn1);
            float p3 = __expf(s[j][3] - mn1);
            sum0 += p0 + p1;
            sum1 += p2 + p3;
            float2 st0, st1;
            st0.x = __uint_as_float(cvt_tf32(p0));
            st0.y = __uint_as_float(cvt_tf32(p1));
            st1.x = __uint_as_float(cvt_tf32(p2));
            st1.y = __uint_as_float(cvt_tf32(p3));
            *reinterpret_cast<float2*>(&Ps[pr0 + 8 * j + 2 * q]) = st0;
            *reinterpret_cast<float2*>(&Ps[pr1 + 8 * j + 2 * q]) = st1;
        }
        sum0 += __shfl_xor_sync(0xffffffffu, sum0, 1);
        sum0 += __shfl_xor_sync(0xffffffffu, sum0, 2);
        sum1 += __shfl_xor_sync(0xffffffffu, sum1, 1);
        sum1 += __shfl_xor_sync(0xffffffffu, sum1, 2);
        li0 = li0 * corr0 + sum0;
        li1 = li1 * corr1 + sum1;
        #pragma unroll
        for (int dt = 0; dt < 8; dt++) {
            o[dt][0] *= corr0; o[dt][1] *= corr0;
            o[dt][2] *= corr1; o[dt][3] *= corr1;
        }
        __syncwarp();   // Ps is per-warp private

        // ---- O += P . V : 8 k-steps x 8 d-tiles ----
        const float* vb = Vs + q * 72 + gr;
        #pragma unroll
        for (int ks = 0; ks < 8; ks++) {
            uint32_t pa[4];
            pa[0] = __float_as_uint(Ps[pr0 + ks * 8 + q]);
            pa[1] = __float_as_uint(Ps[pr1 + ks * 8 + q]);
            pa[2] = __float_as_uint(Ps[pr0 + ks * 8 + q + 4]);
            pa[3] = __float_as_uint(Ps[pr1 + ks * 8 + q + 4]);
            const float* vk = vb + ks * (8 * 72);
            #pragma unroll
            for (int dt = 0; dt < 8; dt++) {
                uint32_t b0 = __float_as_uint(vk[dt * 8]);
                uint32_t b1 = __float_as_uint(vk[4 * 72 + dt * 8]);
                mma_tf32(o[dt], pa, b0, b1);
            }
        }
    }

    // ---- normalize + write a in (B, NX, H*HD) layout ----
    float inv0 = 1.f / li0, inv1 = 1.f / li1;
    int row0 = q0 + w * 16 + gr;
    float* d0 = a_out + ((size_t)(b * kNX + row0)) * kD + h * kHD + 2 * q;
    float* d1 = d0 + 8 * kD;
    #pragma unroll
    for (int dt = 0; dt < 8; dt++) {
        float2 v0 = make_float2(o[dt][0] * inv0, o[dt][1] * inv0);
        float2 v1 = make_float2(o[dt][2] * inv1, o[dt][3] * inv1);
        *reinterpret_cast<float2*>(d0 + dt * 8) = v0;
        *reinterpret_cast<float2*>(d1 + dt * 8) = v1;
    }
}

// ---------------------------------------------------------------------------
extern "C" void kernel_launch(void* const* d_in, const int* in_sizes, int n_in,
                              void* d_out, int out_size)
{
    (void)in_sizes; (void)n_in; (void)out_size;
    const float* x    = (const float*)d_in[0];
    const float* c    = (const float*)d_in[1];
    const int*   mask = (const int*)  d_in[2];
    const float* lnw  = (const float*)d_in[3];
    const float* lnb  = (const float*)d_in[4];
    const float* Wq   = (const float*)d_in[5];
    const float* Wo   = (const float*)d_in[6];

    float* o_out  = (float*)d_out;
    float* kv_out = o_out + (size_t)kB * kNX * kD;

    void *p_xn, *p_q, *p_a, *p_mb;
    cudaGetSymbolAddress(&p_xn, g_xn);
    cudaGetSymbolAddress(&p_q,  g_q);
    cudaGetSymbolAddress(&p_a,  g_a);
    cudaGetSymbolAddress(&p_mb, g_mbits);
    float* xn = (float*)p_xn;
    float* q  = (float*)p_q;
    float* a  = (float*)p_a;
    uint32_t* mb = (uint32_t*)p_mb;

    cudaFuncSetAttribute(attn_kernel,
                         cudaFuncAttributeMaxDynamicSharedMemorySize,
                         SMEM_ATTN_BYTES);

    const int M = kB * kNX;   // 1024

    // 1) mask bit-pack (independent)
    maskbits_kernel<<<(kB * kNX * kNC) / 256, 256>>>(mask, mb);
    // 2) LayerNorm
    ln_kernel<<<M, 256>>>(x, lnw, lnb, xn);
    // 3) q = xn @ Wq
    sgemm_kernel<<<dim3(kD / 64, M / 128), 256>>>(xn, Wq, q, M, kD, kD);
    // 4) kv0 output (independent)
    kv0_kernel<<<(kB * kH * kNC * kHD / 4) / 256, 256>>>(c, (float4*)kv_out);
    // 5) attention (tf32 tensor cores)
    attn_kernel<<<kB * kH * (kNX / 64), 128, SMEM_ATTN_BYTES>>>(q, c, mb, a);
    // 6) o = a @ Wo
    sgemm_kernel<<<dim3(kD / 64, M / 128), 256>>>(a, Wo, o_out, M, kD, kD);
}

// round 15
// speedup vs baseline: 1.1977x; 1.1977x over previous
#include <cuda_runtime.h>
#include <math.h>
#include <stdint.h>

static constexpr int kB  = 2;
static constexpr int kNX = 512;
static constexpr int kNC = 4096;
static constexpr int kD  = 1024;
static constexpr int kH  = 16;
static constexpr int kHD = 64;
#define ATT_SCALE 0.125f   // HD^-0.5

// Scratch (allocation-free rule: __device__ globals)
__device__ float g_xn[kB * kNX * kD];
__device__ float g_q [kB * kNX * kD];
__device__ float g_a [kB * kNX * kD];
__device__ uint32_t g_mbits[(size_t)kB * kNX * kNC / 32];

// ---------------------------------------------------------------------------
// tf32 mma helpers
// ---------------------------------------------------------------------------
__device__ __forceinline__ uint32_t cvt_tf32(float x) {
    uint32_t u;
    asm("cvt.rna.tf32.f32 %0, %1;" : "=r"(u) : "f"(x));
    return u;
}
__device__ __forceinline__ void mma_tf32(float c[4], const uint32_t a[4],
                                         uint32_t b0, uint32_t b1) {
    asm volatile(
        "mma.sync.aligned.m16n8k8.row.col.f32.tf32.tf32.f32 "
        "{%0,%1,%2,%3}, {%4,%5,%6,%7}, {%8,%9}, {%0,%1,%2,%3};"
        : "+f"(c[0]), "+f"(c[1]), "+f"(c[2]), "+f"(c[3])
        : "r"(a[0]), "r"(a[1]), "r"(a[2]), "r"(a[3]), "r"(b0), "r"(b1));
}

// ---------------------------------------------------------------------------
// cp.async helpers
// ---------------------------------------------------------------------------
__device__ __forceinline__ void cpa16(uint32_t dst, const void* src) {
    asm volatile("cp.async.cg.shared.global [%0], [%1], 16;"
                 :: "r"(dst), "l"(src));
}
__device__ __forceinline__ void cp_commit() {
    asm volatile("cp.async.commit_group;" ::: "memory");
}
__device__ __forceinline__ void cp_wait1() {
    asm volatile("cp.async.wait_group 1;" ::: "memory");
}

// ---------------------------------------------------------------------------
// LayerNorm
// ---------------------------------------------------------------------------
__global__ __launch_bounds__(256) void ln_kernel(
    const float* __restrict__ x, const float* __restrict__ w,
    const float* __restrict__ bb, float* __restrict__ out)
{
    int row = blockIdx.x;
    int tid = threadIdx.x;
    float4 v = reinterpret_cast<const float4*>(x + (size_t)row * kD)[tid];
    float s  = v.x + v.y + v.z + v.w;
    float sq = v.x*v.x + v.y*v.y + v.z*v.z + v.w*v.w;
    #pragma unroll
    for (int o = 16; o; o >>= 1) {
        s  += __shfl_xor_sync(0xffffffffu, s,  o);
        sq += __shfl_xor_sync(0xffffffffu, sq, o);
    }
    __shared__ float ss[8], ssq[8];
    int wid = tid >> 5, lid = tid & 31;
    if (lid == 0) { ss[wid] = s; ssq[wid] = sq; }
    __syncthreads();
    if (wid == 0) {
        s  = (lid < 8) ? ss[lid]  : 0.f;
        sq = (lid < 8) ? ssq[lid] : 0.f;
        #pragma unroll
        for (int o = 4; o; o >>= 1) {
            s  += __shfl_xor_sync(0xffffffffu, s,  o);
            sq += __shfl_xor_sync(0xffffffffu, sq, o);
        }
        if (lid == 0) { ss[0] = s; ssq[0] = sq; }
    }
    __syncthreads();
    float mu   = ss[0] * (1.f / kD);
    float var  = ssq[0] * (1.f / kD) - mu * mu;
    float rstd = rsqrtf(var + 1e-5f);
    float4 w4 = reinterpret_cast<const float4*>(w)[tid];
    float4 b4 = reinterpret_cast<const float4*>(bb)[tid];
    float4 o4;
    o4.x = (v.x - mu) * rstd * w4.x + b4.x;
    o4.y = (v.y - mu) * rstd * w4.y + b4.y;
    o4.z = (v.z - mu) * rstd * w4.z + b4.z;
    o4.w = (v.w - mu) * rstd * w4.w + b4.w;
    reinterpret_cast<float4*>(out + (size_t)row * kD)[tid] = o4;
}

// ---------------------------------------------------------------------------
// 3xTF32 split GEMM: C[M,N] = A[M,K] @ B[K,N].  fp32-accurate via
// A=Ahi+Alo, B=Bhi+Blo, C ~= AhiBhi + AhiBlo + AloBhi.
// Block 256 thr (8 warps, 4m x 2n), BM=128 BN=64 BK=32, warp tile 32x32.
// smem: Ah/Al [m][k] stride 36; Bh/Bl [k][n] stride 72.
// ---------------------------------------------------------------------------
static constexpr int TG_AH = 0;                  // 128*36 = 4608
static constexpr int TG_AL = 4608;
static constexpr int TG_BH = 9216;               // 32*72 = 2304
static constexpr int TG_BL = 11520;
static constexpr int TG_TOT = 13824;             // floats
static constexpr int TG_SMEM_BYTES = TG_TOT * 4; // 55296

__global__ __launch_bounds__(256) void tgemm_kernel(
    const float* __restrict__ A, const float* __restrict__ Bm,
    float* __restrict__ C, int M, int N, int K)
{
    extern __shared__ float ts[];
    float* Ah = ts + TG_AH;
    float* Al = ts + TG_AL;
    float* Bh = ts + TG_BH;
    float* Bl = ts + TG_BL;

    int tid  = threadIdx.x;
    int lane = tid & 31, wid = tid >> 5;
    int gr = lane >> 2, qq = lane & 3;
    int wm = wid >> 1, wn = wid & 1;
    int m0 = blockIdx.y * 128, n0 = blockIdx.x * 64;

    float acc[2][4][4];
    #pragma unroll
    for (int mi = 0; mi < 2; mi++)
        #pragma unroll
        for (int ni = 0; ni < 4; ni++)
            #pragma unroll
            for (int e = 0; e < 4; e++) acc[mi][ni][e] = 0.f;

    for (int k0 = 0; k0 < K; k0 += 32) {
        __syncthreads();
        // ---- stage A (hi/lo) ----
        #pragma unroll
        for (int j = 0; j < 4; j++) {
            int f = tid + 256 * j;
            int m = f >> 3, c4 = f & 7;
            float4 v = *reinterpret_cast<const float4*>(
                A + (size_t)(m0 + m) * K + k0 + c4 * 4);
            uint4 hb, lb;
            hb.x = cvt_tf32(v.x); lb.x = cvt_tf32(v.x - __uint_as_float(hb.x));
            hb.y = cvt_tf32(v.y); lb.y = cvt_tf32(v.y - __uint_as_float(hb.y));
            hb.z = cvt_tf32(v.z); lb.z = cvt_tf32(v.z - __uint_as_float(hb.z));
            hb.w = cvt_tf32(v.w); lb.w = cvt_tf32(v.w - __uint_as_float(hb.w));
            *reinterpret_cast<uint4*>(&Ah[m * 36 + c4 * 4]) = hb;
            *reinterpret_cast<uint4*>(&Al[m * 36 + c4 * 4]) = lb;
        }
        // ---- stage B (hi/lo) ----
        #pragma unroll
        for (int j = 0; j < 2; j++) {
            int f = tid + 256 * j;
            int kk = f >> 4, c4 = f & 15;
            float4 v = *reinterpret_cast<const float4*>(
                Bm + (size_t)(k0 + kk) * N + n0 + c4 * 4);
            uint4 hb, lb;
            hb.x = cvt_tf32(v.x); lb.x = cvt_tf32(v.x - __uint_as_float(hb.x));
            hb.y = cvt_tf32(v.y); lb.y = cvt_tf32(v.y - __uint_as_float(hb.y));
            hb.z = cvt_tf32(v.z); lb.z = cvt_tf32(v.z - __uint_as_float(hb.z));
            hb.w = cvt_tf32(v.w); lb.w = cvt_tf32(v.w - __uint_as_float(hb.w));
            *reinterpret_cast<uint4*>(&Bh[kk * 72 + c4 * 4]) = hb;
            *reinterpret_cast<uint4*>(&Bl[kk * 72 + c4 * 4]) = lb;
        }
        __syncthreads();

        #pragma unroll
        for (int ks = 0; ks < 4; ks++) {
            int ko = ks * 8 + qq;
            uint32_t ah[2][4], al[2][4];
            #pragma unroll
            for (int mi = 0; mi < 2; mi++) {
                int row = (wm * 32 + mi * 16 + gr) * 36;
                ah[mi][0] = __float_as_uint(Ah[row + ko]);
                ah[mi][1] = __float_as_uint(Ah[row + 8 * 36 + ko]);
                ah[mi][2] = __float_as_uint(Ah[row + ko + 4]);
                ah[mi][3] = __float_as_uint(Ah[row + 8 * 36 + ko + 4]);
                al[mi][0] = __float_as_uint(Al[row + ko]);
                al[mi][1] = __float_as_uint(Al[row + 8 * 36 + ko]);
                al[mi][2] = __float_as_uint(Al[row + ko + 4]);
                al[mi][3] = __float_as_uint(Al[row + 8 * 36 + ko + 4]);
            }
            #pragma unroll
            for (int ni = 0; ni < 4; ni++) {
                int n = wn * 32 + ni * 8 + gr;
                uint32_t bh0 = __float_as_uint(Bh[ko * 72 + n]);
                uint32_t bh1 = __float_as_uint(Bh[(ko + 4) * 72 + n]);
                uint32_t bl0 = __float_as_uint(Bl[ko * 72 + n]);
                uint32_t bl1 = __float_as_uint(Bl[(ko + 4) * 72 + n]);
                #pragma unroll
                for (int mi = 0; mi < 2; mi++) {
                    mma_tf32(acc[mi][ni], ah[mi], bh0, bh1);
                    mma_tf32(acc[mi][ni], ah[mi], bl0, bl1);
                    mma_tf32(acc[mi][ni], al[mi], bh0, bh1);
                }
            }
        }
    }
    #pragma unroll
    for (int mi = 0; mi < 2; mi++)
        #pragma unroll
        for (int ni = 0; ni < 4; ni++) {
            int row = m0 + wm * 32 + mi * 16 + gr;
            int col = n0 + wn * 32 + ni * 8 + 2 * qq;
            *reinterpret_cast<float2*>(C + (size_t)row * N + col) =
                make_float2(acc[mi][ni][0], acc[mi][ni][1]);
            *reinterpret_cast<float2*>(C + (size_t)(row + 8) * N + col) =
                make_float2(acc[mi][ni][2], acc[mi][ni][3]);
        }
}

// ---------------------------------------------------------------------------
// kv0: out[b][h][n][d] = c[b][n][h*64+d]
// ---------------------------------------------------------------------------
__global__ __launch_bounds__(256) void kv0_kernel(
    const float* __restrict__ c, float4* __restrict__ out)
{
    int i = blockIdx.x * 256 + threadIdx.x;
    int d4 = i & 15;
    int n  = (i >> 4) & (kNC - 1);
    int h  = (i >> 16) & (kH - 1);
    int b  = i >> 20;
    const float4* src = reinterpret_cast<const float4*>(c);
    out[i] = src[(size_t)(b * kNC + n) * (kD / 4) + h * 16 + d4];
}

// ---------------------------------------------------------------------------
// mask bit-pack prepass
// ---------------------------------------------------------------------------
__global__ __launch_bounds__(256) void maskbits_kernel(
    const int* __restrict__ m, uint32_t* __restrict__ bits)
{
    int i = blockIdx.x * 256 + threadIdx.x;
    uint32_t b = __ballot_sync(0xffffffffu, m[i] != 0);
    if ((threadIdx.x & 31) == 0) bits[i >> 5] = b;
}

// ---------------------------------------------------------------------------
// Flash attention, tf32 mma.sync + double-buffered cp.async K/V.
// Block = 128 thr (4 warps), warp = 16 q rows x 64 keys. Grid = 256.
// K/V stored as raw fp32 bits (tf32 truncation in MMA); Q & P use cvt.rna.
// smem: Qs/Ps [64][68] | Ks[2][64][68] | Vs[2][64][72]
// ---------------------------------------------------------------------------
static constexpr int S_QS  = 0;
static constexpr int S_KS  = 64 * 68;                 // 4352
static constexpr int KBUF  = 64 * 68;
static constexpr int S_VS  = S_KS + 2 * KBUF;         // 13056
static constexpr int VBUF  = 64 * 72;
static constexpr int S_TOT = S_VS + 2 * VBUF;         // 22272 floats
static constexpr int SMEM_ATTN_BYTES = S_TOT * 4;     // 89088

__global__ __launch_bounds__(128) void attn_kernel(
    const float* __restrict__ q_s, const float* __restrict__ ctx,
    const uint32_t* __restrict__ bm, float* __restrict__ a_out)
{
    extern __shared__ float sm[];
    float* Qs = sm + S_QS;   // staging for Q, then Ps
    float* Ps = Qs;

    uint32_t sbase = (uint32_t)__cvta_generic_to_shared(sm);

    int tid  = threadIdx.x;
    int lane = tid & 31, w = tid >> 5;
    int gr = lane >> 2, q = lane & 3;
    int qt = blockIdx.x & 7;
    int h  = (blockIdx.x >> 3) & 15;
    int b  = blockIdx.x >> 7;
    int q0 = qt * 64;

    const int NT = kNX / 64 + kNC / 64;   // 72

    // tile source helper
    auto tsrc = [&](int t) -> const float* {
        return (t < 8)
            ? q_s + ((size_t)(b * kNX + t * 64)) * kD + h * kHD
            : ctx + ((size_t)(b * kNC + (t - 8) * 64)) * kD + h * kHD;
    };
    auto issue_tile = [&](int t, int buf) {
        const float* src = tsrc(t);
        uint32_t kd = sbase + (uint32_t)(S_KS + buf * KBUF) * 4;
        uint32_t vd = sbase + (uint32_t)(S_VS + buf * VBUF) * 4;
        #pragma unroll
        for (int j = 0; j < 8; j++) {
            int idx = tid + 128 * j;
            int r = idx >> 4, c4 = idx & 15;
            const float* g = src + (size_t)r * kD + c4 * 4;
            cpa16(kd + (uint32_t)(r * 68 + c4 * 4) * 4, g);
            cpa16(vd + (uint32_t)(r * 72 + c4 * 4) * 4, g);
        }
    };

    // prefetch tile 0
    issue_tile(0, 0);
    cp_commit();

    // ---- stage Q tile (scaled + tf32 RNA) ----
    {
        const float* src = q_s + ((size_t)(b * kNX + q0)) * kD + h * kHD;
        #pragma unroll
        for (int j = 0; j < 8; j++) {
            int idx = tid + 128 * j;
            int r = idx >> 4, c4 = idx & 15;
            float4 v = *reinterpret_cast<const float4*>(src + (size_t)r * kD + c4 * 4);
            uint4 u;
            u.x = cvt_tf32(v.x * ATT_SCALE);
            u.y = cvt_tf32(v.y * ATT_SCALE);
            u.z = cvt_tf32(v.z * ATT_SCALE);
            u.w = cvt_tf32(v.w * ATT_SCALE);
            *reinterpret_cast<uint4*>(&Qs[r * 68 + c4 * 4]) = u;
        }
    }
    __syncthreads();

    // ---- extract Q A-fragments ----
    uint32_t qa[8][4];
    int qr0 = (w * 16 + gr) * 68;
    int qr1 = qr0 + 8 * 68;
    #pragma unroll
    for (int s = 0; s < 8; s++) {
        qa[s][0] = __float_as_uint(Qs[qr0 + s * 8 + q]);
        qa[s][1] = __float_as_uint(Qs[qr1 + s * 8 + q]);
        qa[s][2] = __float_as_uint(Qs[qr0 + s * 8 + q + 4]);
        qa[s][3] = __float_as_uint(Qs[qr1 + s * 8 + q + 4]);
    }
    __syncthreads();   // Qs now free -> Ps

    float o[8][4];
    #pragma unroll
    for (int dt = 0; dt < 8; dt++)
        #pragma unroll
        for (int c = 0; c < 4; c++) o[dt][c] = 0.f;
    float mi0 = -1e30f, mi1 = -1e30f, li0 = 0.f, li1 = 0.f;

    const uint32_t* mrow0 = bm + ((size_t)(b * kNX + q0 + w * 16 + gr)) * (kNC / 32);
    const uint32_t* mrow1 = mrow0 + 8 * (kNC / 32);

    for (int t = 0; t < NT; t++) {
        // issue next tile into the other buffer (prev compute on it is done:
        // trailing __syncthreads of iteration t-1)
        if (t + 1 < NT) issue_tile(t + 1, (t + 1) & 1);
        cp_commit();

        bool masked = (t >= 8);
        uint2 mw0, mw1;
        if (masked) {
            mw0 = *reinterpret_cast<const uint2*>(mrow0 + (t - 8) * 2);
            mw1 = *reinterpret_cast<const uint2*>(mrow1 + (t - 8) * 2);
        }

        cp_wait1();        // tile t landed (one group may still fly)
        __syncthreads();

        const float* Kc = sm + S_KS + (t & 1) * KBUF;
        const float* Vc = sm + S_VS + (t & 1) * VBUF;

        // ---- S = Q . K^T ----
        float s[8][4];
        const float* kb = Kc + gr * 68 + q;
        #pragma unroll
        for (int j = 0; j < 8; j++) {
            s[j][0] = 0.f; s[j][1] = 0.f; s[j][2] = 0.f; s[j][3] = 0.f;
            const float* kj = kb + j * (8 * 68);
            #pragma unroll
            for (int ks = 0; ks < 8; ks++) {
                uint32_t b0 = __float_as_uint(kj[ks * 8]);
                uint32_t b1 = __float_as_uint(kj[ks * 8 + 4]);
                mma_tf32(s[j], qa[ks], b0, b1);
            }
        }

        if (masked) {
            #pragma unroll
            for (int j = 0; j < 8; j++) {
                uint32_t w0 = (j < 4) ? mw0.x : mw0.y;
                uint32_t w1 = (j < 4) ? mw1.x : mw1.y;
                int bit = (8 * j + 2 * q) & 31;
                if (!((w0 >> bit) & 1u))       s[j][0] = -1e30f;
                if (!((w0 >> (bit + 1)) & 1u)) s[j][1] = -1e30f;
                if (!((w1 >> bit) & 1u))       s[j][2] = -1e30f;
                if (!((w1 >> (bit + 1)) & 1u)) s[j][3] = -1e30f;
            }
        }

        // ---- online softmax ----
        float mx0 = -1e30f, mx1 = -1e30f;
        #pragma unroll
        for (int j = 0; j < 8; j++) {
            mx0 = fmaxf(mx0, fmaxf(s[j][0], s[j][1]));
            mx1 = fmaxf(mx1, fmaxf(s[j][2], s[j][3]));
        }
        mx0 = fmaxf(mx0, __shfl_xor_sync(0xffffffffu, mx0, 1));
        mx0 = fmaxf(mx0, __shfl_xor_sync(0xffffffffu, mx0, 2));
        mx1 = fmaxf(mx1, __shfl_xor_sync(0xffffffffu, mx1, 1));
        mx1 = fmaxf(mx1, __shfl_xor_sync(0xffffffffu, mx1, 2));
        float mn0 = fmaxf(mi0, mx0), mn1 = fmaxf(mi1, mx1);
        float corr0 = __expf(mi0 - mn0), corr1 = __expf(mi1 - mn1);
        mi0 = mn0; mi1 = mn1;

        float sum0 = 0.f, sum1 = 0.f;
        #pragma unroll
        for (int j = 0; j < 8; j++) {
            float p0 = __expf(s[j][0] - mn0);
            float p1 = __expf(s[j][1] - mn0);
            float p2 = __expf(s[j][2] - mn1);
            float p3 = __expf(s[j][3] - mn1);
            sum0 += p0 + p1;
            sum1 += p2 + p3;
            float2 st0, st1;
            st0.x = __uint_as_float(cvt_tf32(p0));
            st0.y = __uint_as_float(cvt_tf32(p1));
            st1.x = __uint_as_float(cvt_tf32(p2));
            st1.y = __uint_as_float(cvt_tf32(p3));
            *reinterpret_cast<float2*>(&Ps[qr0 + 8 * j + 2 * q]) = st0;
            *reinterpret_cast<float2*>(&Ps[qr1 + 8 * j + 2 * q]) = st1;
        }
        sum0 += __shfl_xor_sync(0xffffffffu, sum0, 1);
        sum0 += __shfl_xor_sync(0xffffffffu, sum0, 2);
        sum1 += __shfl_xor_sync(0xffffffffu, sum1, 1);
        sum1 += __shfl_xor_sync(0xffffffffu, sum1, 2);
        li0 = li0 * corr0 + sum0;
        li1 = li1 * corr1 + sum1;
        #pragma unroll
        for (int dt = 0; dt < 8; dt++) {
            o[dt][0] *= corr0; o[dt][1] *= corr0;
            o[dt][2] *= corr1; o[dt][3] *= corr1;
        }
        __syncwarp();   // Ps is per-warp private

        // ---- O += P . V ----
        const float* vb = Vc + q * 72 + gr;
        #pragma unroll
        for (int ks = 0; ks < 8; ks++) {
            uint32_t pa[4];
            pa[0] = __float_as_uint(Ps[qr0 + ks * 8 + q]);
            pa[1] = __float_as_uint(Ps[qr1 + ks * 8 + q]);
            pa[2] = __float_as_uint(Ps[qr0 + ks * 8 + q + 4]);
            pa[3] = __float_as_uint(Ps[qr1 + ks * 8 + q + 4]);
            const float* vk = vb + ks * (8 * 72);
            #pragma unroll
            for (int dt = 0; dt < 8; dt++) {
                uint32_t b0 = __float_as_uint(vk[dt * 8]);
                uint32_t b1 = __float_as_uint(vk[4 * 72 + dt * 8]);
                mma_tf32(o[dt], pa, b0, b1);
            }
        }
        __syncthreads();   // compute done -> safe to refill this buffer next iter
    }

    // ---- normalize + write ----
    float inv0 = 1.f / li0, inv1 = 1.f / li1;
    int row0 = q0 + w * 16 + gr;
    float* d0 = a_out + ((size_t)(b * kNX + row0)) * kD + h * kHD + 2 * q;
    float* d1 = d0 + 8 * kD;
    #pragma unroll
    for (int dt = 0; dt < 8; dt++) {
        *reinterpret_cast<float2*>(d0 + dt * 8) =
            make_float2(o[dt][0] * inv0, o[dt][1] * inv0);
        *reinterpret_cast<float2*>(d1 + dt * 8) =
            make_float2(o[dt][2] * inv1, o[dt][3] * inv1);
    }
}

// ---------------------------------------------------------------------------
extern "C" void kernel_launch(void* const* d_in, const int* in_sizes, int n_in,
                              void* d_out, int out_size)
{
    (void)in_sizes; (void)n_in; (void)out_size;
    const float* x    = (const float*)d_in[0];
    const float* c    = (const float*)d_in[1];
    const int*   mask = (const int*)  d_in[2];
    const float* lnw  = (const float*)d_in[3];
    const float* lnb  = (const float*)d_in[4];
    const float* Wq   = (const float*)d_in[5];
    const float* Wo   = (const float*)d_in[6];

    float* o_out  = (float*)d_out;
    float* kv_out = o_out + (size_t)kB * kNX * kD;

    void *p_xn, *p_q, *p_a, *p_mb;
    cudaGetSymbolAddress(&p_xn, g_xn);
    cudaGetSymbolAddress(&p_q,  g_q);
    cudaGetSymbolAddress(&p_a,  g_a);
    cudaGetSymbolAddress(&p_mb, g_mbits);
    float* xn = (float*)p_xn;
    float* q  = (float*)p_q;
    float* a  = (float*)p_a;
    uint32_t* mb = (uint32_t*)p_mb;

    cudaFuncSetAttribute(attn_kernel,
                         cudaFuncAttributeMaxDynamicSharedMemorySize,
                         SMEM_ATTN_BYTES);
    cudaFuncSetAttribute(tgemm_kernel,
                         cudaFuncAttributeMaxDynamicSharedMemorySize,
                         TG_SMEM_BYTES);

    const int M = kB * kNX;   // 1024

    // 1) mask bit-pack (independent)
    maskbits_kernel<<<(kB * kNX * kNC) / 256, 256>>>(mask, mb);
    // 2) LayerNorm
    ln_kernel<<<M, 256>>>(x, lnw, lnb, xn);
    // 3) q = xn @ Wq  (3xTF32, fp32-accurate)
    tgemm_kernel<<<dim3(kD / 64, M / 128), 256, TG_SMEM_BYTES>>>(xn, Wq, q, M, kD, kD);
    // 4) kv0 output (independent)
    kv0_kernel<<<(kB * kH * kNC * kHD / 4) / 256, 256>>>(c, (float4*)kv_out);
    // 5) attention (tf32 tensor cores, cp.async double-buffered)
    attn_kernel<<<kB * kH * (kNX / 64), 128, SMEM_ATTN_BYTES>>>(q, c, mb, a);
    // 6) o = a @ Wo
    tgemm_kernel<<<dim3(kD / 64, M / 128), 256, TG_SMEM_BYTES>>>(a, Wo, o_out, M, kD, kD);
}